// round 1
// baseline (speedup 1.0000x reference)
#include <cuda_runtime.h>
#include <cuda_bf16.h>

// Problem constants (fixed by the dataset)
#define B_  8
#define C_  64
#define O_  64
#define H_  128
#define W_  128
#define HW_ 16384          // H_*W_
#define KH_ 7
#define PAD_ 3
#define R_  49             // KH_*KW_

// Scratch (device globals: no allocation allowed in kernel_launch)
__device__ float g_q[B_ * C_ * HW_];
__device__ float g_k[B_ * C_ * HW_];
__device__ float g_v[B_ * C_ * HW_];
__device__ float g_wt[B_ * R_ * HW_];   // [b][r][h*W+w]

// ---------------------------------------------------------------------------
// Kernel 1: q/k/v = Wm @ x  (per-batch 64x64 GEMM over 16384 pixels)
// grid (HW/128, B, 3), 256 threads. Block computes all 64 outputs x 128 pixels.
// ---------------------------------------------------------------------------
__global__ __launch_bounds__(256) void qkv_kernel(
    const float* __restrict__ x,
    const float* __restrict__ W1,
    const float* __restrict__ W2,
    const float* __restrict__ W3)
{
    __shared__ float sW[64 * 64];    // 16 KB
    __shared__ float sX[64 * 128];   // 32 KB

    const int b  = blockIdx.y;
    const int z  = blockIdx.z;
    const float* Wm = (z == 0) ? W1 : ((z == 1) ? W2 : W3);
    float* out      = (z == 0) ? g_q : ((z == 1) ? g_k : g_v);

    const int tx = threadIdx.x;
    const int n0 = blockIdx.x * 128;

    for (int i = tx; i < 64 * 64; i += 256) sW[i] = Wm[i];

    const float* xb = x + (size_t)b * C_ * HW_ + n0;
    for (int i = tx; i < 64 * 128; i += 256) {
        int c = i >> 7;
        int j = i & 127;
        sX[i] = xb[c * HW_ + j];
    }
    __syncthreads();

    const int p  = tx & 31;          // pixel lane (conflict-free stride-1)
    const int oo = (tx >> 5) * 8;    // 8 output channels per thread

    float acc[8][4];
#pragma unroll
    for (int a = 0; a < 8; a++)
#pragma unroll
        for (int k = 0; k < 4; k++) acc[a][k] = 0.0f;

#pragma unroll 8
    for (int c = 0; c < 64; c++) {
        const float xv0 = sX[c * 128 + p];
        const float xv1 = sX[c * 128 + p + 32];
        const float xv2 = sX[c * 128 + p + 64];
        const float xv3 = sX[c * 128 + p + 96];
#pragma unroll
        for (int a = 0; a < 8; a++) {
            const float w = sW[(oo + a) * 64 + c];   // warp-uniform broadcast
            acc[a][0] = fmaf(w, xv0, acc[a][0]);
            acc[a][1] = fmaf(w, xv1, acc[a][1]);
            acc[a][2] = fmaf(w, xv2, acc[a][2]);
            acc[a][3] = fmaf(w, xv3, acc[a][3]);
        }
    }

    float* ob = out + (size_t)b * O_ * HW_ + n0;
#pragma unroll
    for (int a = 0; a < 8; a++) {
        const int o = oo + a;
        ob[o * HW_ + p]      = acc[a][0];
        ob[o * HW_ + p + 32] = acc[a][1];
        ob[o * HW_ + p + 64] = acc[a][2];
        ob[o * HW_ + p + 96] = acc[a][3];
    }
}

// ---------------------------------------------------------------------------
// Kernel 2: scores (7x7 neighborhood dot products) + softmax -> g_wt
// grid (W/16, H/16, B), 256 threads, 1 thread per pixel.
// smem: k halo tile [64][22][22] + per-thread score scratch [256][49]
// ---------------------------------------------------------------------------
#define K2_SMEM ((64 * 484 + 256 * 49) * 4)

__global__ __launch_bounds__(256) void score_kernel()
{
    extern __shared__ float sm[];
    float* sK = sm;               // 64*484
    float* sS = sm + 64 * 484;    // 256*49, stride 49 (odd -> conflict-free)

    const int b  = blockIdx.z;
    const int h0 = blockIdx.y * 16;
    const int w0 = blockIdx.x * 16;
    const int tx = threadIdx.x;

    // Load zero-padded k halo tile
    const float* kb = g_k + (size_t)b * C_ * HW_;
    for (int i = tx; i < 64 * 484; i += 256) {
        const int c   = i / 484;
        const int rem = i - c * 484;
        const int r   = rem / 22;
        const int col = rem - r * 22;
        const int hh  = h0 + r - PAD_;
        const int ww  = w0 + col - PAD_;
        float v = 0.0f;
        if (hh >= 0 && hh < H_ && ww >= 0 && ww < W_)
            v = kb[c * HW_ + hh * W_ + ww];
        sK[i] = v;
    }

    // q for this thread's pixel -> registers
    const int py = tx >> 4, px = tx & 15;
    const int h = h0 + py, w = w0 + px;
    const float* qb = g_q + (size_t)b * C_ * HW_ + h * W_ + w;
    float q[64];
#pragma unroll
    for (int c = 0; c < 64; c++) q[c] = qb[c * HW_];

    __syncthreads();

    float* myS = sS + tx * 49;

    for (int dh = 0; dh < 7; dh++) {
        const int base0 = (py + dh) * 22 + px;
#pragma unroll 1
        for (int dw = 0; dw < 7; dw++) {
            const float* kp = sK + base0 + dw;
            float a0 = 0.f, a1 = 0.f, a2 = 0.f, a3 = 0.f;
#pragma unroll
            for (int c = 0; c < 64; c += 4) {
                a0 = fmaf(q[c],     kp[(c)     * 484], a0);
                a1 = fmaf(q[c + 1], kp[(c + 1) * 484], a1);
                a2 = fmaf(q[c + 2], kp[(c + 2) * 484], a2);
                a3 = fmaf(q[c + 3], kp[(c + 3) * 484], a3);
            }
            myS[dh * 7 + dw] = (a0 + a1) + (a2 + a3);
        }
    }

    // Softmax over 49 (private scratch, no sync needed)
    float m = -1e30f;
#pragma unroll 1
    for (int r = 0; r < 49; r++) m = fmaxf(m, myS[r]);
    float s = 0.0f;
#pragma unroll 1
    for (int r = 0; r < 49; r++) {
        const float e = __expf(myS[r] - m);
        myS[r] = e;
        s += e;
    }
    const float inv = __frcp_rn(s);

    float* wb = g_wt + (size_t)b * R_ * HW_ + h * W_ + w;
#pragma unroll 1
    for (int r = 0; r < 49; r++) wb[r * HW_] = myS[r] * inv;
}

// ---------------------------------------------------------------------------
// Kernel 3: out[o] = sum_r wt[r] * v_neighbor[o]
// grid (W/16, H/16, B), 256 threads, 1 thread per pixel, 64 output accs.
// smem: v halo tile [64][22][22] + weight tile [49][256]
// ---------------------------------------------------------------------------
#define K3_SMEM ((64 * 484 + 49 * 256) * 4)

__global__ __launch_bounds__(256) void weight_kernel(float* __restrict__ out)
{
    extern __shared__ float sm[];
    float* sV = sm;               // 64*484
    float* sWt = sm + 64 * 484;   // [49][256]

    const int b  = blockIdx.z;
    const int h0 = blockIdx.y * 16;
    const int w0 = blockIdx.x * 16;
    const int tx = threadIdx.x;

    const float* vb = g_v + (size_t)b * C_ * HW_;
    for (int i = tx; i < 64 * 484; i += 256) {
        const int c   = i / 484;
        const int rem = i - c * 484;
        const int r   = rem / 22;
        const int col = rem - r * 22;
        const int hh  = h0 + r - PAD_;
        const int ww  = w0 + col - PAD_;
        float v = 0.0f;
        if (hh >= 0 && hh < H_ && ww >= 0 && ww < W_)
            v = vb[c * HW_ + hh * W_ + ww];
        sV[i] = v;
    }

    const float* wb = g_wt + (size_t)b * R_ * HW_;
    for (int i = tx; i < 49 * 256; i += 256) {
        const int r = i >> 8;
        const int j = i & 255;
        const int hh = h0 + (j >> 4);
        const int ww = w0 + (j & 15);
        sWt[i] = wb[r * HW_ + hh * W_ + ww];
    }
    __syncthreads();

    const int py = tx >> 4, px = tx & 15;

    float acc[64];
#pragma unroll
    for (int o = 0; o < 64; o++) acc[o] = 0.0f;

    for (int dh = 0; dh < 7; dh++) {
        const int base0 = (py + dh) * 22 + px;
#pragma unroll 1
        for (int dw = 0; dw < 7; dw++) {
            const float wv = sWt[(dh * 7 + dw) * 256 + tx];
            const float* vp = sV + base0 + dw;
#pragma unroll
            for (int o = 0; o < 64; o++)
                acc[o] = fmaf(wv, vp[o * 484], acc[o]);
        }
    }

    const int h = h0 + py, w = w0 + px;
    float* op = out + (size_t)b * O_ * HW_ + h * W_ + w;
#pragma unroll
    for (int o = 0; o < 64; o++) op[o * HW_] = acc[o];
}

// ---------------------------------------------------------------------------
extern "C" void kernel_launch(void* const* d_in, const int* in_sizes, int n_in,
                              void* d_out, int out_size)
{
    const float* x  = (const float*)d_in[0];
    const float* W1 = (const float*)d_in[1];
    const float* W2 = (const float*)d_in[2];
    const float* W3 = (const float*)d_in[3];
    float* out = (float*)d_out;
    (void)in_sizes; (void)n_in; (void)out_size;   // kH=kW=7 fixed by dataset

    cudaFuncSetAttribute(score_kernel,
                         cudaFuncAttributeMaxDynamicSharedMemorySize, K2_SMEM);
    cudaFuncSetAttribute(weight_kernel,
                         cudaFuncAttributeMaxDynamicSharedMemorySize, K3_SMEM);

    qkv_kernel<<<dim3(HW_ / 128, B_, 3), 256>>>(x, W1, W2, W3);
    score_kernel<<<dim3(W_ / 16, H_ / 16, B_), 256, K2_SMEM>>>();
    weight_kernel<<<dim3(W_ / 16, H_ / 16, B_), 256, K3_SMEM>>>(out);
}

// round 2
// speedup vs baseline: 1.7825x; 1.7825x over previous
#include <cuda_runtime.h>
#include <cuda_bf16.h>

#define B_   8
#define C_   64
#define O_   64
#define H_   128
#define W_   128
#define HW_  16384
#define PAD_ 3
#define R_   49
#define HSTR 48            // halo row stride: 48 ≡ 16 (mod 32) -> conflict-free 2-row warp reads

// Scratch (device globals)
__device__ float g_y[B_ * C_ * HW_];     // y = (W1^T W2) x
__device__ float g_v[B_ * C_ * HW_];     // v = W3 x
__device__ float g_wt[B_ * R_ * HW_];    // softmax weights [b][r][hw]
__device__ float g_M[64 * 64];           // M = W1^T W2

// -------------------- f32x2 helpers --------------------
__device__ __forceinline__ unsigned long long pk2(float lo, float hi) {
    unsigned long long r;
    asm("mov.b64 %0, {%1, %2};" : "=l"(r) : "f"(lo), "f"(hi));
    return r;
}
__device__ __forceinline__ void fma2(unsigned long long& d,
                                     unsigned long long a, unsigned long long b) {
    asm("fma.rn.f32x2 %0, %1, %2, %0;" : "+l"(d) : "l"(a), "l"(b));
}
__device__ __forceinline__ void upk2(unsigned long long v, float& lo, float& hi) {
    asm("mov.b64 {%0, %1}, %2;" : "=f"(lo), "=f"(hi) : "l"(v));
}

// ---------------------------------------------------------------------------
// Kernel 0: M = W1^T W2   (64x64x64)
// ---------------------------------------------------------------------------
__global__ __launch_bounds__(256) void mat_kernel(
    const float* __restrict__ W1, const float* __restrict__ W2)
{
    __shared__ float s1[4096], s2[4096];
    const int tx = threadIdx.x;
    for (int i = tx; i < 4096; i += 256) { s1[i] = W1[i]; s2[i] = W2[i]; }
    __syncthreads();

    const int c   = tx >> 2;
    const int cp0 = (tx & 3) * 16;
    float acc[16];
#pragma unroll
    for (int j = 0; j < 16; j++) acc[j] = 0.0f;

    for (int o = 0; o < 64; o++) {
        const float a = s1[o * 64 + c];
#pragma unroll
        for (int j = 0; j < 16; j++)
            acc[j] = fmaf(a, s2[o * 64 + cp0 + j], acc[j]);
    }
#pragma unroll
    for (int j = 0; j < 16; j++) g_M[c * 64 + cp0 + j] = acc[j];
}

// ---------------------------------------------------------------------------
// Kernel 1: y = M x  (z=0)  and  v = W3 x  (z=1), f32x2 packed over out-pairs.
// grid (HW/128, B, 2), 256 threads. sWp holds W transposed [c][o], XOR-swizzled.
// ---------------------------------------------------------------------------
__device__ __forceinline__ int wswz(int c, int o) {
    return c * 64 + (o ^ ((c << 1) & 63));   // keeps (o,o+1) pairs adjacent+aligned
}

__global__ __launch_bounds__(256) void qkv_kernel(
    const float* __restrict__ x, const float* __restrict__ W3)
{
    __shared__ __align__(16) float sX[64 * 128];   // 32 KB
    __shared__ __align__(16) float sWp[64 * 64];   // 16 KB  (total = 48 KB exactly)

    const int b = blockIdx.y, z = blockIdx.z;
    const float* Wm = (z == 0) ? g_M : W3;
    float* outp     = (z == 0) ? g_y : g_v;

    const int tx = threadIdx.x;
    const int n0 = blockIdx.x * 128;

    for (int i = tx; i < 4096; i += 256) {
        const int o = i >> 6, c = i & 63;
        sWp[wswz(c, o)] = Wm[i];
    }
    const float* xb = x + (size_t)b * C_ * HW_ + n0;
    for (int i = tx; i < 2048; i += 256) {
        const int c = i >> 5, j = i & 31;
        *(float4*)&sX[c * 128 + j * 4] = *(const float4*)(xb + (size_t)c * HW_ + j * 4);
    }
    __syncthreads();

    const int pp = tx & 31;          // pixel-pair: pixels 2pp,2pp+1 and 64+2pp,64+2pp+1
    const int oo = (tx >> 5) * 8;    // 8 output channels (4 pairs)

    unsigned long long acc[4][4];    // [pixel 0..3][out-pair 0..3]
#pragma unroll
    for (int p = 0; p < 4; p++)
#pragma unroll
        for (int j = 0; j < 4; j++) acc[p][j] = 0ULL;

#pragma unroll 8
    for (int c = 0; c < 64; c++) {
        const float2 xa = *(const float2*)&sX[c * 128 + 2 * pp];
        const float2 xc = *(const float2*)&sX[c * 128 + 64 + 2 * pp];
        const unsigned long long d0 = pk2(xa.x, xa.x);
        const unsigned long long d1 = pk2(xa.y, xa.y);
        const unsigned long long d2 = pk2(xc.x, xc.x);
        const unsigned long long d3 = pk2(xc.y, xc.y);
#pragma unroll
        for (int j = 0; j < 4; j++) {
            const unsigned long long w2 =
                *(const unsigned long long*)&sWp[wswz(c, oo + 2 * j)];
            fma2(acc[0][j], w2, d0);
            fma2(acc[1][j], w2, d1);
            fma2(acc[2][j], w2, d2);
            fma2(acc[3][j], w2, d3);
        }
    }

    float* ob = outp + (size_t)b * O_ * HW_ + n0;
#pragma unroll
    for (int j = 0; j < 4; j++) {
        float a0, a1, b0, b1, c0, c1, d0, d1;
        upk2(acc[0][j], a0, a1);
        upk2(acc[1][j], b0, b1);
        upk2(acc[2][j], c0, c1);
        upk2(acc[3][j], d0, d1);
        const int o = oo + 2 * j;
        *(float2*)(ob + (size_t)o * HW_ + 2 * pp)            = make_float2(a0, b0);
        *(float2*)(ob + (size_t)o * HW_ + 64 + 2 * pp)       = make_float2(c0, d0);
        *(float2*)(ob + (size_t)(o + 1) * HW_ + 2 * pp)      = make_float2(a1, b1);
        *(float2*)(ob + (size_t)(o + 1) * HW_ + 64 + 2 * pp) = make_float2(c1, d1);
    }
}

// ---------------------------------------------------------------------------
// Halo fill helper: 8 channels of [22 x 22] zero-padded tile, row stride HSTR.
// ---------------------------------------------------------------------------
__device__ __forceinline__ void fill_halo(
    float* sH, const float* __restrict__ src, int ch0, int h0, int w0, int tx)
{
    for (int i = tx; i < 8 * 484; i += 256) {
        const int cc  = i / 484;
        const int rem = i - cc * 484;
        const int r   = rem / 22;
        const int col = rem - r * 22;
        const int hh  = h0 + r - PAD_;
        const int ww  = w0 + col - PAD_;
        float v = 0.0f;
        if (hh >= 0 && hh < H_ && ww >= 0 && ww < W_)
            v = src[(size_t)(ch0 + cc) * HW_ + hh * W_ + ww];
        sH[cc * (22 * HSTR) + r * HSTR + col] = v;
    }
}

// ---------------------------------------------------------------------------
// Kernel 2: scores s[p][r] = sum_c x[c,p] * y[c,p+dr]  + softmax -> g_wt
// grid (8, 8, B), 256 threads, 1 px/thread, channel chunks of 8 in smem.
// ---------------------------------------------------------------------------
__global__ __launch_bounds__(256) void score_kernel(const float* __restrict__ x)
{
    __shared__ __align__(16) float sH[8 * 22 * HSTR];   // 33 KB

    const int b  = blockIdx.z;
    const int h0 = blockIdx.y * 16;
    const int w0 = blockIdx.x * 16;
    const int tx = threadIdx.x;
    const int py = tx >> 4, px = tx & 15;
    const int h = h0 + py, w = w0 + px;

    const float* yb = g_y + (size_t)b * C_ * HW_;
    const float* xb = x + (size_t)b * C_ * HW_ + h * W_ + w;

    float s[49];
#pragma unroll
    for (int r = 0; r < 49; r++) s[r] = 0.0f;

    for (int ch0 = 0; ch0 < 64; ch0 += 8) {
        fill_halo(sH, yb, ch0, h0, w0, tx);
        __syncthreads();

        float q[8];
#pragma unroll
        for (int cc = 0; cc < 8; cc++) q[cc] = xb[(size_t)(ch0 + cc) * HW_];

        const float* hpb = sH + py * HSTR + px;
#pragma unroll
        for (int cc = 0; cc < 8; cc++) {
            const float* hp = hpb + cc * (22 * HSTR);
#pragma unroll
            for (int dh = 0; dh < 7; dh++)
#pragma unroll
                for (int dw = 0; dw < 7; dw++)
                    s[dh * 7 + dw] = fmaf(q[cc], hp[dh * HSTR + dw], s[dh * 7 + dw]);
        }
        __syncthreads();
    }

    float m = s[0];
#pragma unroll
    for (int r = 1; r < 49; r++) m = fmaxf(m, s[r]);
    float sum = 0.0f;
#pragma unroll
    for (int r = 0; r < 49; r++) { s[r] = __expf(s[r] - m); sum += s[r]; }
    const float inv = __frcp_rn(sum);

    float* wb = g_wt + (size_t)b * R_ * HW_ + h * W_ + w;
#pragma unroll
    for (int r = 0; r < 49; r++) wb[(size_t)r * HW_] = s[r] * inv;
}

// ---------------------------------------------------------------------------
// Kernel 3: out[o,p] = sum_r wt[r,p] * v[o,p+dr]
// grid (8, 8, B), 256 threads, 1 px/thread, output-channel chunks of 8.
// ---------------------------------------------------------------------------
__global__ __launch_bounds__(256) void weight_kernel(float* __restrict__ out)
{
    __shared__ __align__(16) float sH[8 * 22 * HSTR];

    const int b  = blockIdx.z;
    const int h0 = blockIdx.y * 16;
    const int w0 = blockIdx.x * 16;
    const int tx = threadIdx.x;
    const int py = tx >> 4, px = tx & 15;
    const int h = h0 + py, w = w0 + px;

    const float* vb  = g_v + (size_t)b * C_ * HW_;
    const float* wtb = g_wt + (size_t)b * R_ * HW_ + h * W_ + w;

    float wt[49];
#pragma unroll
    for (int r = 0; r < 49; r++) wt[r] = wtb[(size_t)r * HW_];

    float* ob = out + (size_t)b * O_ * HW_ + h * W_ + w;

    for (int ch0 = 0; ch0 < 64; ch0 += 8) {
        fill_halo(sH, vb, ch0, h0, w0, tx);
        __syncthreads();

        float acc[8];
#pragma unroll
        for (int o = 0; o < 8; o++) acc[o] = 0.0f;

        const float* hpb = sH + py * HSTR + px;
#pragma unroll
        for (int dh = 0; dh < 7; dh++)
#pragma unroll
            for (int dw = 0; dw < 7; dw++) {
                const float wv = wt[dh * 7 + dw];
                const float* hp = hpb + dh * HSTR + dw;
#pragma unroll
                for (int o = 0; o < 8; o++)
                    acc[o] = fmaf(wv, hp[o * (22 * HSTR)], acc[o]);
            }

#pragma unroll
        for (int o = 0; o < 8; o++) ob[(size_t)(ch0 + o) * HW_] = acc[o];
        __syncthreads();
    }
}

// ---------------------------------------------------------------------------
extern "C" void kernel_launch(void* const* d_in, const int* in_sizes, int n_in,
                              void* d_out, int out_size)
{
    const float* x  = (const float*)d_in[0];
    const float* W1 = (const float*)d_in[1];
    const float* W2 = (const float*)d_in[2];
    const float* W3 = (const float*)d_in[3];
    float* out = (float*)d_out;
    (void)in_sizes; (void)n_in; (void)out_size;

    mat_kernel<<<1, 256>>>(W1, W2);
    qkv_kernel<<<dim3(HW_ / 128, B_, 2), 256>>>(x, W3);
    score_kernel<<<dim3(W_ / 16, H_ / 16, B_), 256>>>(x);
    weight_kernel<<<dim3(W_ / 16, H_ / 16, B_), 256>>>(out);
}